// round 15
// baseline (speedup 1.0000x reference)
#include <cuda_runtime.h>
#include <cuda_bf16.h>
#include <cstdint>

#define NN    50000
#define NRL   20
#define DEMB  64
#define DHID  128
#define EMAX  1600000
#define NSEG  (NN * NRL)
#define KT1   (NRL * DEMB + DEMB)
#define KT2   (NRL * DHID + DHID)

// Static scratch (no allocations allowed). 16-byte aligned for uint4 access.
__device__ __align__(16) float g_h1[(long)NN * DHID];
__device__ __align__(16) float g_h2[(long)NN * DHID];
__device__ __align__(16) __nv_bfloat16 g_xh[(long)NN * DHID];    // layer-1 input planes
__device__ __align__(16) __nv_bfloat16 g_xl[(long)NN * DHID];
__device__ __align__(16) __nv_bfloat16 g_yh[(long)NN * DHID];    // layer-2 input planes (h1)
__device__ __align__(16) __nv_bfloat16 g_yl[(long)NN * DHID];
__device__ __align__(16) __nv_bfloat16 g_B1h[128 * KT1];         // layer-1 B^T hi [o][k]
__device__ __align__(16) __nv_bfloat16 g_B1l[128 * KT1];
__device__ __align__(16) __nv_bfloat16 g_B2h[128 * KT2];         // layer-2 B^T hi [o][k]
__device__ __align__(16) __nv_bfloat16 g_B2l[128 * KT2];
__device__ int   g_icnt[NSEG];
__device__ int   g_off[NSEG + 4];
__device__ int   g_pcur[NSEG];
__device__ int   g_bsum[1024];
__device__ int   g_ebuf[EMAX];
__device__ volatile int g_barcnt;
__device__ volatile int g_barsense;

#define SORT_NB   512
#define SORT_IT   2048

// Split a = hi + lo: hi = exact truncation to bf16, lo = residual rounded.
__device__ __forceinline__ void split2(float a, float b, unsigned& h, unsigned& l) {
    unsigned ua = __float_as_uint(a), ub = __float_as_uint(b);
    h = __byte_perm(ua, ub, 0x7632);
    float la = a - __uint_as_float(ua & 0xFFFF0000u);
    float lb = b - __uint_as_float(ub & 0xFFFF0000u);
    __nv_bfloat162 p = __float22bfloat162_rn(make_float2(la, lb));
    l = *reinterpret_cast<unsigned*>(&p);
}

// Sense-reversing grid barrier; all SORT_NB blocks guaranteed resident.
__device__ __forceinline__ void grid_bar() {
    __syncthreads();
    if (threadIdx.x == 0) {
        __threadfence();
        int my = g_barsense;
        int t = atomicAdd((int*)&g_barcnt, 1);
        if (t == SORT_NB - 1) {
            g_barcnt = 0;
            __threadfence();
            atomicAdd((int*)&g_barsense, 1);
        } else {
            while (g_barsense == my) { }
        }
        __threadfence();
    }
    __syncthreads();
}

// prep1: X fp32 -> bf16 planes AND layer-1 B^T hi/lo planes (independent work).
__global__ void prep1_kernel(const float* __restrict__ X,
                             __nv_bfloat16* __restrict__ xh, __nv_bfloat16* __restrict__ xl,
                             const float* __restrict__ W, const float* __restrict__ root,
                             __nv_bfloat16* __restrict__ Bth, __nv_bfloat16* __restrict__ Btl) {
    const long n2 = (long)NN * DEMB / 2;
    const int KA = NRL * DEMB;
    const long tot = n2 + 128 * (KT1 / 2);
    for (long i = (long)blockIdx.x * blockDim.x + threadIdx.x; i < tot;
         i += (long)gridDim.x * blockDim.x) {
        if (i < n2) {
            float2 v = reinterpret_cast<const float2*>(X)[i];
            unsigned h, l;
            split2(v.x, v.y, h, l);
            reinterpret_cast<unsigned*>(xh)[i] = h;
            reinterpret_cast<unsigned*>(xl)[i] = l;
        } else {
            long j = i - n2;
            int o = (int)(j / (KT1 / 2));
            int k = (int)(j % (KT1 / 2)) * 2;
            float b0 = (k < KA) ? W[(long)k * 128 + o] : root[(long)(k - KA) * 128 + o];
            float b1 = (k + 1 < KA) ? W[(long)(k + 1) * 128 + o]
                                    : root[(long)(k + 1 - KA) * 128 + o];
            unsigned h, l;
            split2(b0, b1, h, l);
            *reinterpret_cast<unsigned*>(&Bth[(long)o * KT1 + k]) = h;
            *reinterpret_cast<unsigned*>(&Btl[(long)o * KT1 + k]) = l;
        }
    }
}

__global__ void prepB_kernel(const float* __restrict__ W, const float* __restrict__ root,
                             int KA, int KT,
                             __nv_bfloat16* __restrict__ Bth, __nv_bfloat16* __restrict__ Btl) {
    int i = blockIdx.x * blockDim.x + threadIdx.x;
    int tot = 128 * (KT / 2);
    if (i >= tot) return;
    int o = i / (KT / 2);
    int k = (i % (KT / 2)) * 2;
    float b0 = (k < KA) ? W[(long)k * 128 + o] : root[(long)(k - KA) * 128 + o];
    float b1 = (k + 1 < KA) ? W[(long)(k + 1) * 128 + o] : root[(long)(k + 1 - KA) * 128 + o];
    unsigned h, l;
    split2(b0, b1, h, l);
    *reinterpret_cast<unsigned*>(&Bth[(long)o * KT + k]) = h;
    *reinterpret_cast<unsigned*>(&Btl[(long)o * KT + k]) = l;
}

// ONE-kernel counting sort: zero -> count -> block sums -> offsets -> place.
__global__ void __launch_bounds__(256)
sort_all_kernel(const int* __restrict__ src, const int* __restrict__ dst,
                const int* __restrict__ et, int E,
                int* __restrict__ icnt, int* __restrict__ off, int* __restrict__ pcur,
                int* __restrict__ bsum, int* __restrict__ ebuf) {
    __shared__ int sm[256];
    int tid = threadIdx.x;
    long gt = (long)blockIdx.x * 256 + tid;
    const long gstride = (long)SORT_NB * 256;

    for (long i = gt; i < NSEG; i += gstride) { icnt[i] = 0; pcur[i] = 0; }
    grid_bar();
    for (long i = gt; i < E; i += gstride)
        atomicAdd(&icnt[dst[i] * NRL + et[i]], 1);
    grid_bar();
    {
        int base = blockIdx.x * SORT_IT + tid * 8;
        int s = 0;
#pragma unroll
        for (int t = 0; t < 8; t++) {
            int i = base + t;
            if (i < NSEG) s += icnt[i];
        }
        sm[tid] = s;
        __syncthreads();
        for (int o = 128; o; o >>= 1) {
            if (tid < o) sm[tid] += sm[tid + o];
            __syncthreads();
        }
        if (tid == 0) bsum[blockIdx.x] = sm[0];
    }
    grid_bar();
    {
        int partial = 0;
        for (int j = tid; j < blockIdx.x; j += 256) partial += bsum[j];
        sm[tid] = partial;
        __syncthreads();
        for (int o = 128; o; o >>= 1) {
            if (tid < o) sm[tid] += sm[tid + o];
            __syncthreads();
        }
        int b0 = sm[0];
        __syncthreads();

        int base = blockIdx.x * SORT_IT + tid * 8;
        int v[8], ex[8];
        int s = 0;
#pragma unroll
        for (int t = 0; t < 8; t++) {
            int i = base + t;
            v[t] = (i < NSEG) ? icnt[i] : 0;
            ex[t] = s;
            s += v[t];
        }
        int mine = s;
        sm[tid] = s;
        __syncthreads();
        for (int o = 1; o < 256; o <<= 1) {
            int t = (tid >= o) ? sm[tid - o] : 0;
            __syncthreads();
            sm[tid] += t;
            __syncthreads();
        }
        int tex = sm[tid] - mine;
#pragma unroll
        for (int t = 0; t < 8; t++) {
            int i = base + t;
            if (i < NSEG) off[i] = b0 + tex + ex[t];
        }
        if (blockIdx.x == 0 && tid == 0) off[NSEG] = E;
    }
    grid_bar();
    for (long i = gt; i < E; i += gstride) {
        int seg = dst[i] * NRL + et[i];
        int p = off[seg] + atomicAdd(&pcur[seg], 1);
        ebuf[p] = src[i];
    }
}

#define MMA_BF16(ACC, A, B0, B1)                                              \
    asm volatile(                                                             \
        "mma.sync.aligned.m16n8k16.row.col.f32.bf16.bf16.f32 "                \
        "{%0,%1,%2,%3}, {%4,%5,%6,%7}, {%8,%9}, {%0,%1,%2,%3};"               \
        : "+f"((ACC)[0]), "+f"((ACC)[1]), "+f"((ACC)[2]), "+f"((ACC)[3])      \
        : "r"((A)[0]), "r"((A)[1]), "r"((A)[2]), "r"((A)[3]),                 \
          "r"(B0), "r"(B1))

// FUSED gather+GEMM, M-tile 64 rows, 512 threads (16 warps), 2 blocks/SM.
// Gather: 8 lanes/node (VEC=DIN/32 float4s per lane) -> all 64 nodes of the
// tile gathered in parallel, ONE segment per thread per chunk (no serial
// segment loop). Edges pairwise -> 2*VEC independent X loads in flight.
template <int DIN, int WS>
__global__ void __launch_bounds__(512, 2)
fused_gemm_kernel(const int* __restrict__ ebuf, const int* __restrict__ off,
                  const float* __restrict__ X,
                  const __nv_bfloat16* __restrict__ xh, const __nv_bfloat16* __restrict__ xl,
                  const __nv_bfloat16* __restrict__ Btgh, const __nv_bfloat16* __restrict__ Btgl,
                  const float* __restrict__ bias, float* __restrict__ C,
                  __nv_bfloat16* __restrict__ Ch, __nv_bfloat16* __restrict__ Cl, int relu) {
    const int KT = NRL * DIN + DIN;
    const int PITCH = DIN + 8;
    const int VEC = DIN / 32;         // float4s per lane per edge (2 or 4)

    extern __shared__ __align__(16) char smraw[];
    __nv_bfloat16* Ah  = reinterpret_cast<__nv_bfloat16*>(smraw);
    __nv_bfloat16* Al  = Ah  + 64 * PITCH;
    __nv_bfloat16* Bth = Al  + 64 * PITCH;
    __nv_bfloat16* Btl = Bth + 128 * PITCH;
    int* s_off = reinterpret_cast<int*>(Btl + 128 * PITCH);   // 64*NRL+1 ints

    int tid = threadIdx.x;
    int wid = tid >> 5;
    int lane = tid & 31;
    int wm = wid & 3;        // warp row tile (16 rows)
    int wn = wid >> 2;       // warp col tile (32 cols)
    int bm = blockIdx.x * 64;
    int lg = lane >> 2;
    int lq = lane & 3;

    // ---- cache this block's off[] slice (contiguous, coalesced)
    {
        int nvalid = (NN - bm < 64) ? (NN - bm) : 64;
        int cnt = nvalid * NRL + 1;
        int base = bm * NRL;
        for (int i = tid; i < cnt; i += 512) s_off[i] = off[base + i];
    }
    __syncthreads();

    float acc[4][4];
#pragma unroll
    for (int na = 0; na < 4; na++)
#pragma unroll
        for (int r = 0; r < 4; r++) acc[na][r] = 0.f;

    for (int rel = 0; rel <= NRL; rel++) {
        // ---- B chunk [128 out][DIN] from pre-transposed planes
        {
            const int ELS = 128 * (DIN / 8);
            for (int idx = tid; idx < ELS; idx += 512) {
                int nr = idx / (DIN / 8);
                int c8 = (idx % (DIN / 8)) * 8;
                long go = (long)nr * KT + rel * DIN + c8;
                uint4 vh = *reinterpret_cast<const uint4*>(Btgh + go);
                uint4 vl = *reinterpret_cast<const uint4*>(Btgl + go);
                __nv_bfloat16* ph = Bth + nr * PITCH + c8;
                __nv_bfloat16* pl = Btl + nr * PITCH + c8;
                *reinterpret_cast<uint2*>(ph)     = make_uint2(vh.x, vh.y);
                *reinterpret_cast<uint2*>(ph + 4) = make_uint2(vh.z, vh.w);
                *reinterpret_cast<uint2*>(pl)     = make_uint2(vl.x, vl.y);
                *reinterpret_cast<uint2*>(pl + 4) = make_uint2(vl.z, vl.w);
            }
        }
        // ---- A chunk: rel<NRL gathered mean (1 segment/thread); rel==NRL X rows
        if (rel < NRL) {
            int node = tid >> 3;         // all 64 nodes in parallel
            int l = tid & 7;             // 8 lanes per node, VEC float4s each
            int gn = bm + node;
            int s = node * NRL + rel;
            int bb = s_off[s];
            int n = (gn < NN) ? (s_off[s + 1] - bb) : 0;
            int fe0 = (n > 0) ? __ldg(&ebuf[bb]) : 0;
            int fe1 = (n > 1) ? __ldg(&ebuf[bb + 1]) : 0;

            uint2 h[VEC], lo[VEC];
#pragma unroll
            for (int v = 0; v < VEC; v++) {
                h[v] = make_uint2(0u, 0u);
                lo[v] = make_uint2(0u, 0u);
            }
            if (n == 1) {
                long sid = fe0;
#pragma unroll
                for (int v = 0; v < VEC; v++) {
                    h[v]  = __ldg(reinterpret_cast<const uint2*>(xh + sid * DIN) + l * VEC + v);
                    lo[v] = __ldg(reinterpret_cast<const uint2*>(xl + sid * DIN) + l * VEC + v);
                }
            } else if (n >= 2) {
                float4 a[VEC];
                long s0 = fe0, s1 = fe1;
#pragma unroll
                for (int v = 0; v < VEC; v++) {
                    float4 v0 = __ldg(reinterpret_cast<const float4*>(X + s0 * DIN) + l * VEC + v);
                    float4 v1 = __ldg(reinterpret_cast<const float4*>(X + s1 * DIN) + l * VEC + v);
                    a[v] = make_float4(v0.x + v1.x, v0.y + v1.y, v0.z + v1.z, v0.w + v1.w);
                }
                int e = bb + n, i = bb + 2;
                for (; i + 2 <= e; i += 2) {      // pairwise independent loads
                    long t0 = __ldg(&ebuf[i]);
                    long t1 = __ldg(&ebuf[i + 1]);
#pragma unroll
                    for (int v = 0; v < VEC; v++) {
                        float4 v0 = __ldg(reinterpret_cast<const float4*>(X + t0 * DIN) + l * VEC + v);
                        float4 v1 = __ldg(reinterpret_cast<const float4*>(X + t1 * DIN) + l * VEC + v);
                        a[v].x += v0.x + v1.x; a[v].y += v0.y + v1.y;
                        a[v].z += v0.z + v1.z; a[v].w += v0.w + v1.w;
                    }
                }
                if (i < e) {
                    long t0 = __ldg(&ebuf[i]);
#pragma unroll
                    for (int v = 0; v < VEC; v++) {
                        float4 v0 = __ldg(reinterpret_cast<const float4*>(X + t0 * DIN) + l * VEC + v);
                        a[v].x += v0.x; a[v].y += v0.y; a[v].z += v0.z; a[v].w += v0.w;
                    }
                }
                float sc = 1.f / (float)n;
#pragma unroll
                for (int v = 0; v < VEC; v++) {
                    a[v].x *= sc; a[v].y *= sc; a[v].z *= sc; a[v].w *= sc;
                    split2(a[v].x, a[v].y, h[v].x, lo[v].x);
                    split2(a[v].z, a[v].w, h[v].y, lo[v].y);
                }
            }
#pragma unroll
            for (int v = 0; v < VEC; v++) {
                *reinterpret_cast<uint2*>(Ah + node * PITCH + (l * VEC + v) * 4) = h[v];
                *reinterpret_cast<uint2*>(Al + node * PITCH + (l * VEC + v) * 4) = lo[v];
            }
        } else {
            const int ELS = 64 * (DIN / 8);
            for (int idx = tid; idx < ELS; idx += 512) {
                int node = idx / (DIN / 8);
                int c8 = (idx % (DIN / 8)) * 8;
                int gn = bm + node;
                uint4 vh = make_uint4(0u, 0u, 0u, 0u), vl = make_uint4(0u, 0u, 0u, 0u);
                if (gn < NN) {
                    vh = *reinterpret_cast<const uint4*>(xh + (long)gn * DIN + c8);
                    vl = *reinterpret_cast<const uint4*>(xl + (long)gn * DIN + c8);
                }
                __nv_bfloat16* ph = Ah + node * PITCH + c8;
                __nv_bfloat16* pl = Al + node * PITCH + c8;
                *reinterpret_cast<uint2*>(ph)     = make_uint2(vh.x, vh.y);
                *reinterpret_cast<uint2*>(ph + 4) = make_uint2(vh.z, vh.w);
                *reinterpret_cast<uint2*>(pl)     = make_uint2(vl.x, vl.y);
                *reinterpret_cast<uint2*>(pl + 4) = make_uint2(vl.z, vl.w);
            }
        }
        __syncthreads();

        // ---- MMA over this DIN-wide chunk (3-pass bf16 split), 16x32 warp tile
#pragma unroll
        for (int ks = 0; ks < DIN; ks += 16) {
            unsigned ah[4], al[4];
            {
                int r0 = wm * 16 + lg;
                int kc = ks + lq * 2;
                const __nv_bfloat16* pa = Ah + r0 * PITCH + kc;
                const __nv_bfloat16* pb = Al + r0 * PITCH + kc;
                ah[0] = *reinterpret_cast<const unsigned*>(pa);
                ah[1] = *reinterpret_cast<const unsigned*>(pa + 8 * PITCH);
                ah[2] = *reinterpret_cast<const unsigned*>(pa + 8);
                ah[3] = *reinterpret_cast<const unsigned*>(pa + 8 * PITCH + 8);
                al[0] = *reinterpret_cast<const unsigned*>(pb);
                al[1] = *reinterpret_cast<const unsigned*>(pb + 8 * PITCH);
                al[2] = *reinterpret_cast<const unsigned*>(pb + 8);
                al[3] = *reinterpret_cast<const unsigned*>(pb + 8 * PITCH + 8);
            }
            unsigned bh0[4], bh1[4], bl0[4], bl1[4];
#pragma unroll
            for (int na = 0; na < 4; na++) {
                int nb = wn * 32 + na * 8 + lg;
                int kl = ks + lq * 2;
                const __nv_bfloat16* ph = Bth + nb * PITCH + kl;
                const __nv_bfloat16* pl = Btl + nb * PITCH + kl;
                bh0[na] = *reinterpret_cast<const unsigned*>(ph);
                bh1[na] = *reinterpret_cast<const unsigned*>(ph + 8);
                bl0[na] = *reinterpret_cast<const unsigned*>(pl);
                bl1[na] = *reinterpret_cast<const unsigned*>(pl + 8);
            }
#pragma unroll
            for (int na = 0; na < 4; na++)
                MMA_BF16(acc[na], ah, bh0[na], bh1[na]);
#pragma unroll
            for (int na = 0; na < 4; na++)
                MMA_BF16(acc[na], ah, bl0[na], bl1[na]);
#pragma unroll
            for (int na = 0; na < 4; na++)
                MMA_BF16(acc[na], al, bh0[na], bh1[na]);
        }
        __syncthreads();
    }

    // ---- epilogue: bias(+ReLU), store C; WS=1 also stores bf16 split planes
#pragma unroll
    for (int na = 0; na < 4; na++) {
        int col = wn * 32 + na * 8 + lq * 2;
        float2 bv = *reinterpret_cast<const float2*>(&bias[col]);
        float v0 = acc[na][0] + bv.x;
        float v1 = acc[na][1] + bv.y;
        float v2 = acc[na][2] + bv.x;
        float v3 = acc[na][3] + bv.y;
        if (relu) {
            v0 = fmaxf(v0, 0.f); v1 = fmaxf(v1, 0.f);
            v2 = fmaxf(v2, 0.f); v3 = fmaxf(v3, 0.f);
        }
        int row0 = bm + wm * 16 + lg;
        int row1 = row0 + 8;
        if (row0 < NN) {
            *reinterpret_cast<float2*>(&C[(long)row0 * DHID + col]) = make_float2(v0, v1);
            if (WS) {
                unsigned h, l;
                split2(v0, v1, h, l);
                *reinterpret_cast<unsigned*>(&Ch[(long)row0 * DHID + col]) = h;
                *reinterpret_cast<unsigned*>(&Cl[(long)row0 * DHID + col]) = l;
            }
        }
        if (row1 < NN) {
            *reinterpret_cast<float2*>(&C[(long)row1 * DHID + col]) = make_float2(v2, v3);
            if (WS) {
                unsigned h, l;
                split2(v2, v3, h, l);
                *reinterpret_cast<unsigned*>(&Ch[(long)row1 * DHID + col]) = h;
                *reinterpret_cast<unsigned*>(&Cl[(long)row1 * DHID + col]) = l;
            }
        }
    }
}

__global__ void decoder_kernel(const int* __restrict__ head, const int* __restrict__ tail,
                               const int* __restrict__ rel, const float* __restrict__ h,
                               const float* __restrict__ rel_emb, float* __restrict__ out,
                               int Bn) {
    int warp = (blockIdx.x * blockDim.x + threadIdx.x) >> 5;
    int lane = threadIdx.x & 31;
    if (warp >= Bn) return;
    const float4* hp = reinterpret_cast<const float4*>(h + (long)head[warp] * DHID);
    const float4* tp = reinterpret_cast<const float4*>(h + (long)tail[warp] * DHID);
    const float4* rp = reinterpret_cast<const float4*>(rel_emb + (long)rel[warp] * DHID);
    float4 a = hp[lane], b = tp[lane], c = rp[lane];
    float s = a.x * b.x * c.x + a.y * b.y * c.y + a.z * b.z * c.z + a.w * b.w * c.w;
#pragma unroll
    for (int o = 16; o; o >>= 1) s += __shfl_xor_sync(0xffffffffu, s, o);
    if (lane == 0) out[warp] = s;
}

extern "C" void kernel_launch(void* const* d_in, const int* in_sizes, int n_in,
                              void* d_out, int out_size) {
    const int*   edge_index = (const int*)d_in[0];
    const int*   edge_type  = (const int*)d_in[1];
    const int*   head       = (const int*)d_in[2];
    const int*   tail       = (const int*)d_in[3];
    const int*   rel        = (const int*)d_in[4];
    const float* node_emb   = (const float*)d_in[5];
    const float* W1         = (const float*)d_in[6];
    const float* root1      = (const float*)d_in[7];
    const float* b1         = (const float*)d_in[8];
    const float* W2         = (const float*)d_in[9];
    const float* root2      = (const float*)d_in[10];
    const float* b2         = (const float*)d_in[11];
    const float* rel_emb    = (const float*)d_in[12];

    int E = in_sizes[0] / 2;
    const int* src = edge_index;
    const int* dst = edge_index + E;

    __nv_bfloat16 *xh, *xl, *yh, *yl, *B1h, *B1l, *B2h, *B2l;
    float *h1, *h2;
    int *icnt, *off, *pcur, *bsum, *ebuf;
    cudaGetSymbolAddress((void**)&xh, g_xh);
    cudaGetSymbolAddress((void**)&xl, g_xl);
    cudaGetSymbolAddress((void**)&yh, g_yh);
    cudaGetSymbolAddress((void**)&yl, g_yl);
    cudaGetSymbolAddress((void**)&B1h, g_B1h);
    cudaGetSymbolAddress((void**)&B1l, g_B1l);
    cudaGetSymbolAddress((void**)&B2h, g_B2h);
    cudaGetSymbolAddress((void**)&B2l, g_B2l);
    cudaGetSymbolAddress((void**)&h1, g_h1);
    cudaGetSymbolAddress((void**)&h2, g_h2);
    cudaGetSymbolAddress((void**)&icnt, g_icnt);
    cudaGetSymbolAddress((void**)&off, g_off);
    cudaGetSymbolAddress((void**)&pcur, g_pcur);
    cudaGetSymbolAddress((void**)&bsum, g_bsum);
    cudaGetSymbolAddress((void**)&ebuf, g_ebuf);

    const int T = 256;
    const int KA2 = NRL * DHID;
    const int OFFB = (64 * NRL + 1 + 3) / 4 * 4 * 4;
    const int SM1 = 384 * (DEMB + 8) * 2 + OFFB;   // 60432 B
    const int SM2 = 384 * (DHID + 8) * 2 + OFFB;   // 109584 B -> 2 blocks/SM

    cudaFuncSetAttribute((const void*)fused_gemm_kernel<DEMB, 1>,
                         cudaFuncAttributeMaxDynamicSharedMemorySize, SM1);
    cudaFuncSetAttribute((const void*)fused_gemm_kernel<DHID, 0>,
                         cudaFuncAttributeMaxDynamicSharedMemorySize, SM2);

    // 1) independent prep: X planes + layer-1 B planes
    prep1_kernel<<<592, T>>>(node_emb, xh, xl, W1, root1, B1h, B1l);
    // 2) one-kernel counting sort (grid-resident barrier)
    sort_all_kernel<<<SORT_NB, T>>>(src, dst, edge_type, E, icnt, off, pcur, bsum, ebuf);
    // 3) layer-2 B planes
    prepB_kernel<<<(128 * KT2 / 2 + T - 1) / T, T>>>(W2, root2, KA2, KT2, B2h, B2l);
    // 4) layer 1 fused gather+GEMM (epilogue emits h1 planes)
    fused_gemm_kernel<DEMB, 1><<<(NN + 63) / 64, 512, SM1>>>(
        ebuf, off, node_emb, xh, xl, B1h, B1l, b1, h1, yh, yl, 1);
    // 5) layer 2
    fused_gemm_kernel<DHID, 0><<<(NN + 63) / 64, 512, SM2>>>(
        ebuf, off, h1, yh, yl, B2h, B2l, b2, h2, nullptr, nullptr, 0);
    // 6) DistMult decoder
    int Bn = in_sizes[2];
    decoder_kernel<<<(Bn * 32 + T - 1) / T, T>>>(head, tail, rel, h2, rel_emb,
                                                 (float*)d_out, Bn);
}

// round 16
// speedup vs baseline: 1.0537x; 1.0537x over previous
#include <cuda_runtime.h>
#include <cuda_bf16.h>
#include <cstdint>

#define NN    50000
#define NRL   20
#define DEMB  64
#define DHID  128
#define EMAX  1600000
#define NSEG  (NN * NRL)
#define KT1   (NRL * DEMB + DEMB)
#define KT2   (NRL * DHID + DHID)

// Static scratch (no allocations allowed). 16-byte aligned for uint4 access.
__device__ __align__(16) float g_h1[(long)NN * DHID];
__device__ __align__(16) float g_h2[(long)NN * DHID];
__device__ __align__(16) __nv_bfloat16 g_xh[(long)NN * DHID];    // layer-1 input planes
__device__ __align__(16) __nv_bfloat16 g_xl[(long)NN * DHID];
__device__ __align__(16) __nv_bfloat16 g_yh[(long)NN * DHID];    // layer-2 input planes (h1)
__device__ __align__(16) __nv_bfloat16 g_yl[(long)NN * DHID];
__device__ __align__(16) __nv_bfloat16 g_B1h[128 * KT1];         // layer-1 B^T hi [o][k]
__device__ __align__(16) __nv_bfloat16 g_B1l[128 * KT1];
__device__ __align__(16) __nv_bfloat16 g_B2h[128 * KT2];         // layer-2 B^T hi [o][k]
__device__ __align__(16) __nv_bfloat16 g_B2l[128 * KT2];
__device__ int   g_icnt[NSEG];
__device__ int   g_off[NSEG + 4];
__device__ int   g_pcur[NSEG];
__device__ int   g_bsum[1024];
__device__ int   g_ebuf[EMAX];
__device__ volatile int g_barcnt;
__device__ volatile int g_barsense;

#define SORT_NB   512
#define SORT_IT   2048

// Split a = hi + lo: hi = exact truncation to bf16, lo = residual rounded.
__device__ __forceinline__ void split2(float a, float b, unsigned& h, unsigned& l) {
    unsigned ua = __float_as_uint(a), ub = __float_as_uint(b);
    h = __byte_perm(ua, ub, 0x7632);
    float la = a - __uint_as_float(ua & 0xFFFF0000u);
    float lb = b - __uint_as_float(ub & 0xFFFF0000u);
    __nv_bfloat162 p = __float22bfloat162_rn(make_float2(la, lb));
    l = *reinterpret_cast<unsigned*>(&p);
}

// Sense-reversing grid barrier; all SORT_NB blocks guaranteed resident.
__device__ __forceinline__ void grid_bar() {
    __syncthreads();
    if (threadIdx.x == 0) {
        __threadfence();
        int my = g_barsense;
        int t = atomicAdd((int*)&g_barcnt, 1);
        if (t == SORT_NB - 1) {
            g_barcnt = 0;
            __threadfence();
            atomicAdd((int*)&g_barsense, 1);
        } else {
            while (g_barsense == my) { }
        }
        __threadfence();
    }
    __syncthreads();
}

// prep1: X fp32 -> bf16 planes AND layer-1 B^T hi/lo planes (independent work).
__global__ void prep1_kernel(const float* __restrict__ X,
                             __nv_bfloat16* __restrict__ xh, __nv_bfloat16* __restrict__ xl,
                             const float* __restrict__ W, const float* __restrict__ root,
                             __nv_bfloat16* __restrict__ Bth, __nv_bfloat16* __restrict__ Btl) {
    const long n2 = (long)NN * DEMB / 2;
    const int KA = NRL * DEMB;
    const long tot = n2 + 128 * (KT1 / 2);
    for (long i = (long)blockIdx.x * blockDim.x + threadIdx.x; i < tot;
         i += (long)gridDim.x * blockDim.x) {
        if (i < n2) {
            float2 v = reinterpret_cast<const float2*>(X)[i];
            unsigned h, l;
            split2(v.x, v.y, h, l);
            reinterpret_cast<unsigned*>(xh)[i] = h;
            reinterpret_cast<unsigned*>(xl)[i] = l;
        } else {
            long j = i - n2;
            int o = (int)(j / (KT1 / 2));
            int k = (int)(j % (KT1 / 2)) * 2;
            float b0 = (k < KA) ? W[(long)k * 128 + o] : root[(long)(k - KA) * 128 + o];
            float b1 = (k + 1 < KA) ? W[(long)(k + 1) * 128 + o]
                                    : root[(long)(k + 1 - KA) * 128 + o];
            unsigned h, l;
            split2(b0, b1, h, l);
            *reinterpret_cast<unsigned*>(&Bth[(long)o * KT1 + k]) = h;
            *reinterpret_cast<unsigned*>(&Btl[(long)o * KT1 + k]) = l;
        }
    }
}

__global__ void prepB_kernel(const float* __restrict__ W, const float* __restrict__ root,
                             int KA, int KT,
                             __nv_bfloat16* __restrict__ Bth, __nv_bfloat16* __restrict__ Btl) {
    int i = blockIdx.x * blockDim.x + threadIdx.x;
    int tot = 128 * (KT / 2);
    if (i >= tot) return;
    int o = i / (KT / 2);
    int k = (i % (KT / 2)) * 2;
    float b0 = (k < KA) ? W[(long)k * 128 + o] : root[(long)(k - KA) * 128 + o];
    float b1 = (k + 1 < KA) ? W[(long)(k + 1) * 128 + o] : root[(long)(k + 1 - KA) * 128 + o];
    unsigned h, l;
    split2(b0, b1, h, l);
    *reinterpret_cast<unsigned*>(&Bth[(long)o * KT + k]) = h;
    *reinterpret_cast<unsigned*>(&Btl[(long)o * KT + k]) = l;
}

// ONE-kernel counting sort: zero -> count -> block sums -> offsets -> place.
__global__ void __launch_bounds__(256)
sort_all_kernel(const int* __restrict__ src, const int* __restrict__ dst,
                const int* __restrict__ et, int E,
                int* __restrict__ icnt, int* __restrict__ off, int* __restrict__ pcur,
                int* __restrict__ bsum, int* __restrict__ ebuf) {
    __shared__ int sm[256];
    int tid = threadIdx.x;
    long gt = (long)blockIdx.x * 256 + tid;
    const long gstride = (long)SORT_NB * 256;

    for (long i = gt; i < NSEG; i += gstride) { icnt[i] = 0; pcur[i] = 0; }
    grid_bar();
    for (long i = gt; i < E; i += gstride)
        atomicAdd(&icnt[dst[i] * NRL + et[i]], 1);
    grid_bar();
    {
        int base = blockIdx.x * SORT_IT + tid * 8;
        int s = 0;
#pragma unroll
        for (int t = 0; t < 8; t++) {
            int i = base + t;
            if (i < NSEG) s += icnt[i];
        }
        sm[tid] = s;
        __syncthreads();
        for (int o = 128; o; o >>= 1) {
            if (tid < o) sm[tid] += sm[tid + o];
            __syncthreads();
        }
        if (tid == 0) bsum[blockIdx.x] = sm[0];
    }
    grid_bar();
    {
        int partial = 0;
        for (int j = tid; j < blockIdx.x; j += 256) partial += bsum[j];
        sm[tid] = partial;
        __syncthreads();
        for (int o = 128; o; o >>= 1) {
            if (tid < o) sm[tid] += sm[tid + o];
            __syncthreads();
        }
        int b0 = sm[0];
        __syncthreads();

        int base = blockIdx.x * SORT_IT + tid * 8;
        int v[8], ex[8];
        int s = 0;
#pragma unroll
        for (int t = 0; t < 8; t++) {
            int i = base + t;
            v[t] = (i < NSEG) ? icnt[i] : 0;
            ex[t] = s;
            s += v[t];
        }
        int mine = s;
        sm[tid] = s;
        __syncthreads();
        for (int o = 1; o < 256; o <<= 1) {
            int t = (tid >= o) ? sm[tid - o] : 0;
            __syncthreads();
            sm[tid] += t;
            __syncthreads();
        }
        int tex = sm[tid] - mine;
#pragma unroll
        for (int t = 0; t < 8; t++) {
            int i = base + t;
            if (i < NSEG) off[i] = b0 + tex + ex[t];
        }
        if (blockIdx.x == 0 && tid == 0) off[NSEG] = E;
    }
    grid_bar();
    for (long i = gt; i < E; i += gstride) {
        int seg = dst[i] * NRL + et[i];
        int p = off[seg] + atomicAdd(&pcur[seg], 1);
        ebuf[p] = src[i];
    }
}

#define MMA_BF16(ACC, A, B0, B1)                                              \
    asm volatile(                                                             \
        "mma.sync.aligned.m16n8k16.row.col.f32.bf16.bf16.f32 "                \
        "{%0,%1,%2,%3}, {%4,%5,%6,%7}, {%8,%9}, {%0,%1,%2,%3};"               \
        : "+f"((ACC)[0]), "+f"((ACC)[1]), "+f"((ACC)[2]), "+f"((ACC)[3])      \
        : "r"((A)[0]), "r"((A)[1]), "r"((A)[2]), "r"((A)[3]),                 \
          "r"(B0), "r"(B1))

// FUSED gather+GEMM, M-tile 64 rows, 512 threads (16 warps), 2 blocks/SM.
// LN = lanes per node (per-layer tuned): layer1 LN=8 (64 nodes parallel,
// NIT=1), layer2 LN=16 (32 nodes parallel, NIT=2). VEC=2 float4s/lane both.
template <int DIN, int LN, int WS>
__global__ void __launch_bounds__(512, 2)
fused_gemm_kernel(const int* __restrict__ ebuf, const int* __restrict__ off,
                  const float* __restrict__ X,
                  const __nv_bfloat16* __restrict__ xh, const __nv_bfloat16* __restrict__ xl,
                  const __nv_bfloat16* __restrict__ Btgh, const __nv_bfloat16* __restrict__ Btgl,
                  const float* __restrict__ bias, float* __restrict__ C,
                  __nv_bfloat16* __restrict__ Ch, __nv_bfloat16* __restrict__ Cl, int relu) {
    const int KT = NRL * DIN + DIN;
    const int PITCH = DIN + 8;
    const int VEC = DIN / (4 * LN);   // float4s per lane per edge
    const int G = 512 / LN;           // nodes gathered in parallel
    const int NIT = 64 / G;           // serial segments per thread

    extern __shared__ __align__(16) char smraw[];
    __nv_bfloat16* Ah  = reinterpret_cast<__nv_bfloat16*>(smraw);
    __nv_bfloat16* Al  = Ah  + 64 * PITCH;
    __nv_bfloat16* Bth = Al  + 64 * PITCH;
    __nv_bfloat16* Btl = Bth + 128 * PITCH;
    int* s_off = reinterpret_cast<int*>(Btl + 128 * PITCH);   // 64*NRL+1 ints

    int tid = threadIdx.x;
    int wid = tid >> 5;
    int lane = tid & 31;
    int wm = wid & 3;        // warp row tile (16 rows)
    int wn = wid >> 2;       // warp col tile (32 cols)
    int bm = blockIdx.x * 64;
    int lg = lane >> 2;
    int lq = lane & 3;

    // ---- cache this block's off[] slice (contiguous, coalesced)
    {
        int nvalid = (NN - bm < 64) ? (NN - bm) : 64;
        int cnt = nvalid * NRL + 1;
        int base = bm * NRL;
        for (int i = tid; i < cnt; i += 512) s_off[i] = off[base + i];
    }
    __syncthreads();

    float acc[4][4];
#pragma unroll
    for (int na = 0; na < 4; na++)
#pragma unroll
        for (int r = 0; r < 4; r++) acc[na][r] = 0.f;

    for (int rel = 0; rel <= NRL; rel++) {
        // ---- B chunk [128 out][DIN] from pre-transposed planes
        {
            const int ELS = 128 * (DIN / 8);
            for (int idx = tid; idx < ELS; idx += 512) {
                int nr = idx / (DIN / 8);
                int c8 = (idx % (DIN / 8)) * 8;
                long go = (long)nr * KT + rel * DIN + c8;
                uint4 vh = *reinterpret_cast<const uint4*>(Btgh + go);
                uint4 vl = *reinterpret_cast<const uint4*>(Btgl + go);
                __nv_bfloat16* ph = Bth + nr * PITCH + c8;
                __nv_bfloat16* pl = Btl + nr * PITCH + c8;
                *reinterpret_cast<uint2*>(ph)     = make_uint2(vh.x, vh.y);
                *reinterpret_cast<uint2*>(ph + 4) = make_uint2(vh.z, vh.w);
                *reinterpret_cast<uint2*>(pl)     = make_uint2(vl.x, vl.y);
                *reinterpret_cast<uint2*>(pl + 4) = make_uint2(vl.z, vl.w);
            }
        }
        // ---- A chunk: rel<NRL gathered mean; rel==NRL X rows (root term)
        if (rel < NRL) {
            int g = tid / LN;
            int l = tid % LN;
            int bs[NIT], ns[NIT];
#pragma unroll
            for (int it = 0; it < NIT; it++) {
                int node = it * G + g;
                int gn = bm + node;
                int s = node * NRL + rel;
                int bb = s_off[s];
                bs[it] = bb;
                ns[it] = (gn < NN) ? (s_off[s + 1] - bb) : 0;
            }
            int fe0[NIT], fe1[NIT];
#pragma unroll
            for (int it = 0; it < NIT; it++) {
                fe0[it] = (ns[it] > 0) ? __ldg(&ebuf[bs[it]]) : 0;
                fe1[it] = (ns[it] > 1) ? __ldg(&ebuf[bs[it] + 1]) : 0;
            }
#pragma unroll
            for (int it = 0; it < NIT; it++) {
                int node = it * G + g;
                int n = ns[it];
                uint2 h[VEC], lo[VEC];
#pragma unroll
                for (int v = 0; v < VEC; v++) {
                    h[v] = make_uint2(0u, 0u);
                    lo[v] = make_uint2(0u, 0u);
                }
                if (n == 1) {
                    long sid = fe0[it];
#pragma unroll
                    for (int v = 0; v < VEC; v++) {
                        h[v]  = __ldg(reinterpret_cast<const uint2*>(xh + sid * DIN) + l * VEC + v);
                        lo[v] = __ldg(reinterpret_cast<const uint2*>(xl + sid * DIN) + l * VEC + v);
                    }
                } else if (n >= 2) {
                    float4 a[VEC];
                    long s0 = fe0[it], s1 = fe1[it];
#pragma unroll
                    for (int v = 0; v < VEC; v++) {
                        float4 v0 = __ldg(reinterpret_cast<const float4*>(X + s0 * DIN) + l * VEC + v);
                        float4 v1 = __ldg(reinterpret_cast<const float4*>(X + s1 * DIN) + l * VEC + v);
                        a[v] = make_float4(v0.x + v1.x, v0.y + v1.y, v0.z + v1.z, v0.w + v1.w);
                    }
                    int e = bs[it] + n, i = bs[it] + 2;
                    for (; i + 2 <= e; i += 2) {      // pairwise independent loads
                        long t0 = __ldg(&ebuf[i]);
                        long t1 = __ldg(&ebuf[i + 1]);
#pragma unroll
                        for (int v = 0; v < VEC; v++) {
                            float4 v0 = __ldg(reinterpret_cast<const float4*>(X + t0 * DIN) + l * VEC + v);
                            float4 v1 = __ldg(reinterpret_cast<const float4*>(X + t1 * DIN) + l * VEC + v);
                            a[v].x += v0.x + v1.x; a[v].y += v0.y + v1.y;
                            a[v].z += v0.z + v1.z; a[v].w += v0.w + v1.w;
                        }
                    }
                    if (i < e) {
                        long t0 = __ldg(&ebuf[i]);
#pragma unroll
                        for (int v = 0; v < VEC; v++) {
                            float4 v0 = __ldg(reinterpret_cast<const float4*>(X + t0 * DIN) + l * VEC + v);
                            a[v].x += v0.x; a[v].y += v0.y; a[v].z += v0.z; a[v].w += v0.w;
                        }
                    }
                    float sc = 1.f / (float)n;
#pragma unroll
                    for (int v = 0; v < VEC; v++) {
                        a[v].x *= sc; a[v].y *= sc; a[v].z *= sc; a[v].w *= sc;
                        split2(a[v].x, a[v].y, h[v].x, lo[v].x);
                        split2(a[v].z, a[v].w, h[v].y, lo[v].y);
                    }
                }
#pragma unroll
                for (int v = 0; v < VEC; v++) {
                    *reinterpret_cast<uint2*>(Ah + node * PITCH + (l * VEC + v) * 4) = h[v];
                    *reinterpret_cast<uint2*>(Al + node * PITCH + (l * VEC + v) * 4) = lo[v];
                }
            }
        } else {
            const int ELS = 64 * (DIN / 8);
            for (int idx = tid; idx < ELS; idx += 512) {
                int node = idx / (DIN / 8);
                int c8 = (idx % (DIN / 8)) * 8;
                int gn = bm + node;
                uint4 vh = make_uint4(0u, 0u, 0u, 0u), vl = make_uint4(0u, 0u, 0u, 0u);
                if (gn < NN) {
                    vh = *reinterpret_cast<const uint4*>(xh + (long)gn * DIN + c8);
                    vl = *reinterpret_cast<const uint4*>(xl + (long)gn * DIN + c8);
                }
                __nv_bfloat16* ph = Ah + node * PITCH + c8;
                __nv_bfloat16* pl = Al + node * PITCH + c8;
                *reinterpret_cast<uint2*>(ph)     = make_uint2(vh.x, vh.y);
                *reinterpret_cast<uint2*>(ph + 4) = make_uint2(vh.z, vh.w);
                *reinterpret_cast<uint2*>(pl)     = make_uint2(vl.x, vl.y);
                *reinterpret_cast<uint2*>(pl + 4) = make_uint2(vl.z, vl.w);
            }
        }
        __syncthreads();

        // ---- MMA over this DIN-wide chunk (3-pass bf16 split), 16x32 warp tile
#pragma unroll
        for (int ks = 0; ks < DIN; ks += 16) {
            unsigned ah[4], al[4];
            {
                int r0 = wm * 16 + lg;
                int kc = ks + lq * 2;
                const __nv_bfloat16* pa = Ah + r0 * PITCH + kc;
                const __nv_bfloat16* pb = Al + r0 * PITCH + kc;
                ah[0] = *reinterpret_cast<const unsigned*>(pa);
                ah[1] = *reinterpret_cast<const unsigned*>(pa + 8 * PITCH);
                ah[2] = *reinterpret_cast<const unsigned*>(pa + 8);
                ah[3] = *reinterpret_cast<const unsigned*>(pa + 8 * PITCH + 8);
                al[0] = *reinterpret_cast<const unsigned*>(pb);
                al[1] = *reinterpret_cast<const unsigned*>(pb + 8 * PITCH);
                al[2] = *reinterpret_cast<const unsigned*>(pb + 8);
                al[3] = *reinterpret_cast<const unsigned*>(pb + 8 * PITCH + 8);
            }
            unsigned bh0[4], bh1[4], bl0[4], bl1[4];
#pragma unroll
            for (int na = 0; na < 4; na++) {
                int nb = wn * 32 + na * 8 + lg;
                int kl = ks + lq * 2;
                const __nv_bfloat16* ph = Bth + nb * PITCH + kl;
                const __nv_bfloat16* pl = Btl + nb * PITCH + kl;
                bh0[na] = *reinterpret_cast<const unsigned*>(ph);
                bh1[na] = *reinterpret_cast<const unsigned*>(ph + 8);
                bl0[na] = *reinterpret_cast<const unsigned*>(pl);
                bl1[na] = *reinterpret_cast<const unsigned*>(pl + 8);
            }
#pragma unroll
            for (int na = 0; na < 4; na++)
                MMA_BF16(acc[na], ah, bh0[na], bh1[na]);
#pragma unroll
            for (int na = 0; na < 4; na++)
                MMA_BF16(acc[na], ah, bl0[na], bl1[na]);
#pragma unroll
            for (int na = 0; na < 4; na++)
                MMA_BF16(acc[na], al, bh0[na], bh1[na]);
        }
        __syncthreads();
    }

    // ---- epilogue: bias(+ReLU), store C; WS=1 also stores bf16 split planes
#pragma unroll
    for (int na = 0; na < 4; na++) {
        int col = wn * 32 + na * 8 + lq * 2;
        float2 bv = *reinterpret_cast<const float2*>(&bias[col]);
        float v0 = acc[na][0] + bv.x;
        float v1 = acc[na][1] + bv.y;
        float v2 = acc[na][2] + bv.x;
        float v3 = acc[na][3] + bv.y;
        if (relu) {
            v0 = fmaxf(v0, 0.f); v1 = fmaxf(v1, 0.f);
            v2 = fmaxf(v2, 0.f); v3 = fmaxf(v3, 0.f);
        }
        int row0 = bm + wm * 16 + lg;
        int row1 = row0 + 8;
        if (row0 < NN) {
            *reinterpret_cast<float2*>(&C[(long)row0 * DHID + col]) = make_float2(v0, v1);
            if (WS) {
                unsigned h, l;
                split2(v0, v1, h, l);
                *reinterpret_cast<unsigned*>(&Ch[(long)row0 * DHID + col]) = h;
                *reinterpret_cast<unsigned*>(&Cl[(long)row0 * DHID + col]) = l;
            }
        }
        if (row1 < NN) {
            *reinterpret_cast<float2*>(&C[(long)row1 * DHID + col]) = make_float2(v2, v3);
            if (WS) {
                unsigned h, l;
                split2(v2, v3, h, l);
                *reinterpret_cast<unsigned*>(&Ch[(long)row1 * DHID + col]) = h;
                *reinterpret_cast<unsigned*>(&Cl[(long)row1 * DHID + col]) = l;
            }
        }
    }
}

__global__ void decoder_kernel(const int* __restrict__ head, const int* __restrict__ tail,
                               const int* __restrict__ rel, const float* __restrict__ h,
                               const float* __restrict__ rel_emb, float* __restrict__ out,
                               int Bn) {
    int warp = (blockIdx.x * blockDim.x + threadIdx.x) >> 5;
    int lane = threadIdx.x & 31;
    if (warp >= Bn) return;
    const float4* hp = reinterpret_cast<const float4*>(h + (long)head[warp] * DHID);
    const float4* tp = reinterpret_cast<const float4*>(h + (long)tail[warp] * DHID);
    const float4* rp = reinterpret_cast<const float4*>(rel_emb + (long)rel[warp] * DHID);
    float4 a = hp[lane], b = tp[lane], c = rp[lane];
    float s = a.x * b.x * c.x + a.y * b.y * c.y + a.z * b.z * c.z + a.w * b.w * c.w;
#pragma unroll
    for (int o = 16; o; o >>= 1) s += __shfl_xor_sync(0xffffffffu, s, o);
    if (lane == 0) out[warp] = s;
}

extern "C" void kernel_launch(void* const* d_in, const int* in_sizes, int n_in,
                              void* d_out, int out_size) {
    const int*   edge_index = (const int*)d_in[0];
    const int*   edge_type  = (const int*)d_in[1];
    const int*   head       = (const int*)d_in[2];
    const int*   tail       = (const int*)d_in[3];
    const int*   rel        = (const int*)d_in[4];
    const float* node_emb   = (const float*)d_in[5];
    const float* W1         = (const float*)d_in[6];
    const float* root1      = (const float*)d_in[7];
    const float* b1         = (const float*)d_in[8];
    const float* W2         = (const float*)d_in[9];
    const float* root2      = (const float*)d_in[10];
    const float* b2         = (const float*)d_in[11];
    const float* rel_emb    = (const float*)d_in[12];

    int E = in_sizes[0] / 2;
    const int* src = edge_index;
    const int* dst = edge_index + E;

    __nv_bfloat16 *xh, *xl, *yh, *yl, *B1h, *B1l, *B2h, *B2l;
    float *h1, *h2;
    int *icnt, *off, *pcur, *bsum, *ebuf;
    cudaGetSymbolAddress((void**)&xh, g_xh);
    cudaGetSymbolAddress((void**)&xl, g_xl);
    cudaGetSymbolAddress((void**)&yh, g_yh);
    cudaGetSymbolAddress((void**)&yl, g_yl);
    cudaGetSymbolAddress((void**)&B1h, g_B1h);
    cudaGetSymbolAddress((void**)&B1l, g_B1l);
    cudaGetSymbolAddress((void**)&B2h, g_B2h);
    cudaGetSymbolAddress((void**)&B2l, g_B2l);
    cudaGetSymbolAddress((void**)&h1, g_h1);
    cudaGetSymbolAddress((void**)&h2, g_h2);
    cudaGetSymbolAddress((void**)&icnt, g_icnt);
    cudaGetSymbolAddress((void**)&off, g_off);
    cudaGetSymbolAddress((void**)&pcur, g_pcur);
    cudaGetSymbolAddress((void**)&bsum, g_bsum);
    cudaGetSymbolAddress((void**)&ebuf, g_ebuf);

    const int T = 256;
    const int KA2 = NRL * DHID;
    const int OFFB = (64 * NRL + 1 + 3) / 4 * 4 * 4;
    const int SM1 = 384 * (DEMB + 8) * 2 + OFFB;   // 60432 B
    const int SM2 = 384 * (DHID + 8) * 2 + OFFB;   // 109584 B -> 2 blocks/SM

    cudaFuncSetAttribute((const void*)fused_gemm_kernel<DEMB, 8, 1>,
                         cudaFuncAttributeMaxDynamicSharedMemorySize, SM1);
    cudaFuncSetAttribute((const void*)fused_gemm_kernel<DHID, 16, 0>,
                         cudaFuncAttributeMaxDynamicSharedMemorySize, SM2);

    // 1) independent prep: X planes + layer-1 B planes
    prep1_kernel<<<592, T>>>(node_emb, xh, xl, W1, root1, B1h, B1l);
    // 2) one-kernel counting sort (grid-resident barrier)
    sort_all_kernel<<<SORT_NB, T>>>(src, dst, edge_type, E, icnt, off, pcur, bsum, ebuf);
    // 3) layer-2 B planes
    prepB_kernel<<<(128 * KT2 / 2 + T - 1) / T, T>>>(W2, root2, KA2, KT2, B2h, B2l);
    // 4) layer 1 fused gather+GEMM (LN=8: whole tile parallel, NIT=1)
    fused_gemm_kernel<DEMB, 8, 1><<<(NN + 63) / 64, 512, SM1>>>(
        ebuf, off, node_emb, xh, xl, B1h, B1l, b1, h1, yh, yl, 1);
    // 5) layer 2 (LN=16: VEC=2, NIT=2 — best measured config for DIN=128)
    fused_gemm_kernel<DHID, 16, 0><<<(NN + 63) / 64, 512, SM2>>>(
        ebuf, off, h1, yh, yl, B2h, B2l, b2, h2, nullptr, nullptr, 0);
    // 6) DistMult decoder
    int Bn = in_sizes[2];
    decoder_kernel<<<(Bn * 32 + T - 1) / T, T>>>(head, tail, rel, h2, rel_emb,
                                                 (float*)d_out, Bn);
}

// round 17
// speedup vs baseline: 1.1425x; 1.0843x over previous
#include <cuda_runtime.h>
#include <cuda_bf16.h>
#include <cstdint>

#define NN    50000
#define NRL   20
#define DEMB  64
#define DHID  128
#define EMAX  1600000
#define NSEG  (NN * NRL)
#define KT1   (NRL * DEMB + DEMB)
#define KT2   (NRL * DHID + DHID)

// Static scratch (no allocations allowed). 16-byte aligned for uint4 access.
__device__ __align__(16) float g_h1[(long)NN * DHID];
__device__ __align__(16) float g_h2[(long)NN * DHID];
__device__ __align__(16) __nv_bfloat16 g_xh[(long)NN * DHID];    // layer-1 input planes
__device__ __align__(16) __nv_bfloat16 g_xl[(long)NN * DHID];
__device__ __align__(16) __nv_bfloat16 g_yh[(long)NN * DHID];    // layer-2 input planes (h1)
__device__ __align__(16) __nv_bfloat16 g_yl[(long)NN * DHID];
__device__ __align__(16) __nv_bfloat16 g_B1h[128 * KT1];         // layer-1 B^T hi [o][k]
__device__ __align__(16) __nv_bfloat16 g_B1l[128 * KT1];
__device__ __align__(16) __nv_bfloat16 g_B2h[128 * KT2];         // layer-2 B^T hi [o][k]
__device__ __align__(16) __nv_bfloat16 g_B2l[128 * KT2];
__device__ int   g_icnt[NSEG];
__device__ int   g_off[NSEG + 4];
__device__ int   g_pcur[NSEG];
__device__ int   g_bsum[1024];
__device__ int   g_ebuf[EMAX];
__device__ volatile int g_barcnt;
__device__ volatile int g_barsense;

#define SORT_NB   512
#define SORT_IT   2048

__device__ __forceinline__ uint32_t smem_u32(const void* p) {
    uint32_t a;
    asm("{ .reg .u64 t; cvta.to.shared.u64 t, %1; cvt.u32.u64 %0, t; }" : "=r"(a) : "l"(p));
    return a;
}

#define LDMX4(R, ADDR)                                                        \
    asm volatile("ldmatrix.sync.aligned.m8n8.x4.shared.b16 {%0,%1,%2,%3}, [%4];" \
                 : "=r"((R)[0]), "=r"((R)[1]), "=r"((R)[2]), "=r"((R)[3])     \
                 : "r"(ADDR))

// Split a = hi + lo: hi = exact truncation to bf16, lo = residual rounded.
__device__ __forceinline__ void split2(float a, float b, unsigned& h, unsigned& l) {
    unsigned ua = __float_as_uint(a), ub = __float_as_uint(b);
    h = __byte_perm(ua, ub, 0x7632);
    float la = a - __uint_as_float(ua & 0xFFFF0000u);
    float lb = b - __uint_as_float(ub & 0xFFFF0000u);
    __nv_bfloat162 p = __float22bfloat162_rn(make_float2(la, lb));
    l = *reinterpret_cast<unsigned*>(&p);
}

// Sense-reversing grid barrier; all SORT_NB blocks guaranteed resident.
__device__ __forceinline__ void grid_bar() {
    __syncthreads();
    if (threadIdx.x == 0) {
        __threadfence();
        int my = g_barsense;
        int t = atomicAdd((int*)&g_barcnt, 1);
        if (t == SORT_NB - 1) {
            g_barcnt = 0;
            __threadfence();
            atomicAdd((int*)&g_barsense, 1);
        } else {
            while (g_barsense == my) { }
        }
        __threadfence();
    }
    __syncthreads();
}

// prep1: X fp32 -> bf16 planes AND layer-1 B^T hi/lo planes (independent work).
__global__ void prep1_kernel(const float* __restrict__ X,
                             __nv_bfloat16* __restrict__ xh, __nv_bfloat16* __restrict__ xl,
                             const float* __restrict__ W, const float* __restrict__ root,
                             __nv_bfloat16* __restrict__ Bth, __nv_bfloat16* __restrict__ Btl) {
    const long n2 = (long)NN * DEMB / 2;
    const int KA = NRL * DEMB;
    const long tot = n2 + 128 * (KT1 / 2);
    for (long i = (long)blockIdx.x * blockDim.x + threadIdx.x; i < tot;
         i += (long)gridDim.x * blockDim.x) {
        if (i < n2) {
            float2 v = reinterpret_cast<const float2*>(X)[i];
            unsigned h, l;
            split2(v.x, v.y, h, l);
            reinterpret_cast<unsigned*>(xh)[i] = h;
            reinterpret_cast<unsigned*>(xl)[i] = l;
        } else {
            long j = i - n2;
            int o = (int)(j / (KT1 / 2));
            int k = (int)(j % (KT1 / 2)) * 2;
            float b0 = (k < KA) ? W[(long)k * 128 + o] : root[(long)(k - KA) * 128 + o];
            float b1 = (k + 1 < KA) ? W[(long)(k + 1) * 128 + o]
                                    : root[(long)(k + 1 - KA) * 128 + o];
            unsigned h, l;
            split2(b0, b1, h, l);
            *reinterpret_cast<unsigned*>(&Bth[(long)o * KT1 + k]) = h;
            *reinterpret_cast<unsigned*>(&Btl[(long)o * KT1 + k]) = l;
        }
    }
}

__global__ void prepB_kernel(const float* __restrict__ W, const float* __restrict__ root,
                             int KA, int KT,
                             __nv_bfloat16* __restrict__ Bth, __nv_bfloat16* __restrict__ Btl) {
    int i = blockIdx.x * blockDim.x + threadIdx.x;
    int tot = 128 * (KT / 2);
    if (i >= tot) return;
    int o = i / (KT / 2);
    int k = (i % (KT / 2)) * 2;
    float b0 = (k < KA) ? W[(long)k * 128 + o] : root[(long)(k - KA) * 128 + o];
    float b1 = (k + 1 < KA) ? W[(long)(k + 1) * 128 + o] : root[(long)(k + 1 - KA) * 128 + o];
    unsigned h, l;
    split2(b0, b1, h, l);
    *reinterpret_cast<unsigned*>(&Bth[(long)o * KT + k]) = h;
    *reinterpret_cast<unsigned*>(&Btl[(long)o * KT + k]) = l;
}

// ONE-kernel counting sort: zero -> count -> block sums -> offsets -> place.
__global__ void __launch_bounds__(256)
sort_all_kernel(const int* __restrict__ src, const int* __restrict__ dst,
                const int* __restrict__ et, int E,
                int* __restrict__ icnt, int* __restrict__ off, int* __restrict__ pcur,
                int* __restrict__ bsum, int* __restrict__ ebuf) {
    __shared__ int sm[256];
    int tid = threadIdx.x;
    long gt = (long)blockIdx.x * 256 + tid;
    const long gstride = (long)SORT_NB * 256;

    for (long i = gt; i < NSEG; i += gstride) { icnt[i] = 0; pcur[i] = 0; }
    grid_bar();
    for (long i = gt; i < E; i += gstride)
        atomicAdd(&icnt[dst[i] * NRL + et[i]], 1);
    grid_bar();
    {
        int base = blockIdx.x * SORT_IT + tid * 8;
        int s = 0;
#pragma unroll
        for (int t = 0; t < 8; t++) {
            int i = base + t;
            if (i < NSEG) s += icnt[i];
        }
        sm[tid] = s;
        __syncthreads();
        for (int o = 128; o; o >>= 1) {
            if (tid < o) sm[tid] += sm[tid + o];
            __syncthreads();
        }
        if (tid == 0) bsum[blockIdx.x] = sm[0];
    }
    grid_bar();
    {
        int partial = 0;
        for (int j = tid; j < blockIdx.x; j += 256) partial += bsum[j];
        sm[tid] = partial;
        __syncthreads();
        for (int o = 128; o; o >>= 1) {
            if (tid < o) sm[tid] += sm[tid + o];
            __syncthreads();
        }
        int b0 = sm[0];
        __syncthreads();

        int base = blockIdx.x * SORT_IT + tid * 8;
        int v[8], ex[8];
        int s = 0;
#pragma unroll
        for (int t = 0; t < 8; t++) {
            int i = base + t;
            v[t] = (i < NSEG) ? icnt[i] : 0;
            ex[t] = s;
            s += v[t];
        }
        int mine = s;
        sm[tid] = s;
        __syncthreads();
        for (int o = 1; o < 256; o <<= 1) {
            int t = (tid >= o) ? sm[tid - o] : 0;
            __syncthreads();
            sm[tid] += t;
            __syncthreads();
        }
        int tex = sm[tid] - mine;
#pragma unroll
        for (int t = 0; t < 8; t++) {
            int i = base + t;
            if (i < NSEG) off[i] = b0 + tex + ex[t];
        }
        if (blockIdx.x == 0 && tid == 0) off[NSEG] = E;
    }
    grid_bar();
    for (long i = gt; i < E; i += gstride) {
        int seg = dst[i] * NRL + et[i];
        int p = off[seg] + atomicAdd(&pcur[seg], 1);
        ebuf[p] = src[i];
    }
}

#define MMA_BF16(ACC, A, B0, B1)                                              \
    asm volatile(                                                             \
        "mma.sync.aligned.m16n8k16.row.col.f32.bf16.bf16.f32 "                \
        "{%0,%1,%2,%3}, {%4,%5,%6,%7}, {%8,%9}, {%0,%1,%2,%3};"               \
        : "+f"((ACC)[0]), "+f"((ACC)[1]), "+f"((ACC)[2]), "+f"((ACC)[3])      \
        : "r"((A)[0]), "r"((A)[1]), "r"((A)[2]), "r"((A)[3]),                 \
          "r"(B0), "r"(B1))

// FUSED gather+GEMM, M-tile 64 rows, 512 threads (16 warps), 2 blocks/SM.
// LN per-layer tuned (8 for DIN=64, 16 for DIN=128). MMA fragment loads via
// ldmatrix.x4 (6 LDSM vs 24 LDS.32 per k-step) — layouts verified identical.
template <int DIN, int LN, int WS>
__global__ void __launch_bounds__(512, 2)
fused_gemm_kernel(const int* __restrict__ ebuf, const int* __restrict__ off,
                  const float* __restrict__ X,
                  const __nv_bfloat16* __restrict__ xh, const __nv_bfloat16* __restrict__ xl,
                  const __nv_bfloat16* __restrict__ Btgh, const __nv_bfloat16* __restrict__ Btgl,
                  const float* __restrict__ bias, float* __restrict__ C,
                  __nv_bfloat16* __restrict__ Ch, __nv_bfloat16* __restrict__ Cl, int relu) {
    const int KT = NRL * DIN + DIN;
    const int PITCH = DIN + 8;
    const int VEC = DIN / (4 * LN);   // float4s per lane per edge
    const int G = 512 / LN;           // nodes gathered in parallel
    const int NIT = 64 / G;           // serial segments per thread

    extern __shared__ __align__(16) char smraw[];
    __nv_bfloat16* Ah  = reinterpret_cast<__nv_bfloat16*>(smraw);
    __nv_bfloat16* Al  = Ah  + 64 * PITCH;
    __nv_bfloat16* Bth = Al  + 64 * PITCH;
    __nv_bfloat16* Btl = Bth + 128 * PITCH;
    int* s_off = reinterpret_cast<int*>(Btl + 128 * PITCH);   // 64*NRL+1 ints

    int tid = threadIdx.x;
    int wid = tid >> 5;
    int lane = tid & 31;
    int wm = wid & 3;        // warp row tile (16 rows)
    int wn = wid >> 2;       // warp col tile (32 cols)
    int bm = blockIdx.x * 64;
    int lg = lane >> 2;
    int lq = lane & 3;

    // ldmatrix base addresses (bytes, shared space)
    // A x4: mats = [rows 0-7 @k], [rows 8-15 @k], [rows 0-7 @k+8], [rows 8-15 @k+8]
    //   lane 0-15 -> row wm*16+(lane&15) @k ; lane 16-31 -> same rows @k+8
    uint32_t aAh = smem_u32(Ah) + ((wm * 16 + (lane & 15)) * PITCH + (lane >> 4) * 8) * 2;
    uint32_t aAl = smem_u32(Al) + ((wm * 16 + (lane & 15)) * PITCH + (lane >> 4) * 8) * 2;
    // B x4 (@k): mats = na 0..3 tiles; lane -> row wn*32+lane
    uint32_t aBh = smem_u32(Bth) + (wn * 32 + lane) * PITCH * 2;
    uint32_t aBl = smem_u32(Btl) + (wn * 32 + lane) * PITCH * 2;

    // ---- cache this block's off[] slice (contiguous, coalesced)
    {
        int nvalid = (NN - bm < 64) ? (NN - bm) : 64;
        int cnt = nvalid * NRL + 1;
        int base = bm * NRL;
        for (int i = tid; i < cnt; i += 512) s_off[i] = off[base + i];
    }
    __syncthreads();

    float acc[4][4];
#pragma unroll
    for (int na = 0; na < 4; na++)
#pragma unroll
        for (int r = 0; r < 4; r++) acc[na][r] = 0.f;

    for (int rel = 0; rel <= NRL; rel++) {
        // ---- B chunk [128 out][DIN] from pre-transposed planes
        {
            const int ELS = 128 * (DIN / 8);
            for (int idx = tid; idx < ELS; idx += 512) {
                int nr = idx / (DIN / 8);
                int c8 = (idx % (DIN / 8)) * 8;
                long go = (long)nr * KT + rel * DIN + c8;
                uint4 vh = *reinterpret_cast<const uint4*>(Btgh + go);
                uint4 vl = *reinterpret_cast<const uint4*>(Btgl + go);
                __nv_bfloat16* ph = Bth + nr * PITCH + c8;
                __nv_bfloat16* pl = Btl + nr * PITCH + c8;
                *reinterpret_cast<uint2*>(ph)     = make_uint2(vh.x, vh.y);
                *reinterpret_cast<uint2*>(ph + 4) = make_uint2(vh.z, vh.w);
                *reinterpret_cast<uint2*>(pl)     = make_uint2(vl.x, vl.y);
                *reinterpret_cast<uint2*>(pl + 4) = make_uint2(vl.z, vl.w);
            }
        }
        // ---- A chunk: rel<NRL gathered mean; rel==NRL X rows (root term)
        if (rel < NRL) {
            int g = tid / LN;
            int l = tid % LN;
            int bs[NIT], ns[NIT];
#pragma unroll
            for (int it = 0; it < NIT; it++) {
                int node = it * G + g;
                int gn = bm + node;
                int s = node * NRL + rel;
                int bb = s_off[s];
                bs[it] = bb;
                ns[it] = (gn < NN) ? (s_off[s + 1] - bb) : 0;
            }
            int fe0[NIT], fe1[NIT];
#pragma unroll
            for (int it = 0; it < NIT; it++) {
                fe0[it] = (ns[it] > 0) ? __ldg(&ebuf[bs[it]]) : 0;
                fe1[it] = (ns[it] > 1) ? __ldg(&ebuf[bs[it] + 1]) : 0;
            }
#pragma unroll
            for (int it = 0; it < NIT; it++) {
                int node = it * G + g;
                int n = ns[it];
                uint2 h[VEC], lo[VEC];
#pragma unroll
                for (int v = 0; v < VEC; v++) {
                    h[v] = make_uint2(0u, 0u);
                    lo[v] = make_uint2(0u, 0u);
                }
                if (n == 1) {
                    long sid = fe0[it];
#pragma unroll
                    for (int v = 0; v < VEC; v++) {
                        h[v]  = __ldg(reinterpret_cast<const uint2*>(xh + sid * DIN) + l * VEC + v);
                        lo[v] = __ldg(reinterpret_cast<const uint2*>(xl + sid * DIN) + l * VEC + v);
                    }
                } else if (n >= 2) {
                    float4 a[VEC];
                    long s0 = fe0[it], s1 = fe1[it];
#pragma unroll
                    for (int v = 0; v < VEC; v++) {
                        float4 v0 = __ldg(reinterpret_cast<const float4*>(X + s0 * DIN) + l * VEC + v);
                        float4 v1 = __ldg(reinterpret_cast<const float4*>(X + s1 * DIN) + l * VEC + v);
                        a[v] = make_float4(v0.x + v1.x, v0.y + v1.y, v0.z + v1.z, v0.w + v1.w);
                    }
                    int e = bs[it] + n, i = bs[it] + 2;
                    for (; i + 2 <= e; i += 2) {      // pairwise independent loads
                        long t0 = __ldg(&ebuf[i]);
                        long t1 = __ldg(&ebuf[i + 1]);
#pragma unroll
                        for (int v = 0; v < VEC; v++) {
                            float4 v0 = __ldg(reinterpret_cast<const float4*>(X + t0 * DIN) + l * VEC + v);
                            float4 v1 = __ldg(reinterpret_cast<const float4*>(X + t1 * DIN) + l * VEC + v);
                            a[v].x += v0.x + v1.x; a[v].y += v0.y + v1.y;
                            a[v].z += v0.z + v1.z; a[v].w += v0.w + v1.w;
                        }
                    }
                    if (i < e) {
                        long t0 = __ldg(&ebuf[i]);
#pragma unroll
                        for (int v = 0; v < VEC; v++) {
                            float4 v0 = __ldg(reinterpret_cast<const float4*>(X + t0 * DIN) + l * VEC + v);
                            a[v].x += v0.x; a[v].y += v0.y; a[v].z += v0.z; a[v].w += v0.w;
                        }
                    }
                    float sc = 1.f / (float)n;
#pragma unroll
                    for (int v = 0; v < VEC; v++) {
                        a[v].x *= sc; a[v].y *= sc; a[v].z *= sc; a[v].w *= sc;
                        split2(a[v].x, a[v].y, h[v].x, lo[v].x);
                        split2(a[v].z, a[v].w, h[v].y, lo[v].y);
                    }
                }
#pragma unroll
                for (int v = 0; v < VEC; v++) {
                    *reinterpret_cast<uint2*>(Ah + node * PITCH + (l * VEC + v) * 4) = h[v];
                    *reinterpret_cast<uint2*>(Al + node * PITCH + (l * VEC + v) * 4) = lo[v];
                }
            }
        } else {
            const int ELS = 64 * (DIN / 8);
            for (int idx = tid; idx < ELS; idx += 512) {
                int node = idx / (DIN / 8);
                int c8 = (idx % (DIN / 8)) * 8;
                int gn = bm + node;
                uint4 vh = make_uint4(0u, 0u, 0u, 0u), vl = make_uint4(0u, 0u, 0u, 0u);
                if (gn < NN) {
                    vh = *reinterpret_cast<const uint4*>(xh + (long)gn * DIN + c8);
                    vl = *reinterpret_cast<const uint4*>(xl + (long)gn * DIN + c8);
                }
                __nv_bfloat16* ph = Ah + node * PITCH + c8;
                __nv_bfloat16* pl = Al + node * PITCH + c8;
                *reinterpret_cast<uint2*>(ph)     = make_uint2(vh.x, vh.y);
                *reinterpret_cast<uint2*>(ph + 4) = make_uint2(vh.z, vh.w);
                *reinterpret_cast<uint2*>(pl)     = make_uint2(vl.x, vl.y);
                *reinterpret_cast<uint2*>(pl + 4) = make_uint2(vl.z, vl.w);
            }
        }
        __syncthreads();

        // ---- MMA over this DIN-wide chunk (3-pass bf16 split), ldmatrix loads
#pragma unroll
        for (int ks = 0; ks < DIN; ks += 16) {
            unsigned ah[4], al[4], bh0[4], bh1[4], bl0[4], bl1[4];
            LDMX4(ah, aAh + ks * 2);
            LDMX4(al, aAl + ks * 2);
            LDMX4(bh0, aBh + ks * 2);
            LDMX4(bh1, aBh + ks * 2 + 16);
            LDMX4(bl0, aBl + ks * 2);
            LDMX4(bl1, aBl + ks * 2 + 16);
#pragma unroll
            for (int na = 0; na < 4; na++)
                MMA_BF16(acc[na], ah, bh0[na], bh1[na]);
#pragma unroll
            for (int na = 0; na < 4; na++)
                MMA_BF16(acc[na], ah, bl0[na], bl1[na]);
#pragma unroll
            for (int na = 0; na < 4; na++)
                MMA_BF16(acc[na], al, bh0[na], bh1[na]);
        }
        __syncthreads();
    }

    // ---- epilogue: bias(+ReLU), store C; WS=1 also stores bf16 split planes
#pragma unroll
    for (int na = 0; na < 4; na++) {
        int col = wn * 32 + na * 8 + lq * 2;
        float2 bv = *reinterpret_cast<const float2*>(&bias[col]);
        float v0 = acc[na][0] + bv.x;
        float v1 = acc[na][1] + bv.y;
        float v2 = acc[na][2] + bv.x;
        float v3 = acc[na][3] + bv.y;
        if (relu) {
            v0 = fmaxf(v0, 0.f); v1 = fmaxf(v1, 0.f);
            v2 = fmaxf(v2, 0.f); v3 = fmaxf(v3, 0.f);
        }
        int row0 = bm + wm * 16 + lg;
        int row1 = row0 + 8;
        if (row0 < NN) {
            *reinterpret_cast<float2*>(&C[(long)row0 * DHID + col]) = make_float2(v0, v1);
            if (WS) {
                unsigned h, l;
                split2(v0, v1, h, l);
                *reinterpret_cast<unsigned*>(&Ch[(long)row0 * DHID + col]) = h;
                *reinterpret_cast<unsigned*>(&Cl[(long)row0 * DHID + col]) = l;
            }
        }
        if (row1 < NN) {
            *reinterpret_cast<float2*>(&C[(long)row1 * DHID + col]) = make_float2(v2, v3);
            if (WS) {
                unsigned h, l;
                split2(v2, v3, h, l);
                *reinterpret_cast<unsigned*>(&Ch[(long)row1 * DHID + col]) = h;
                *reinterpret_cast<unsigned*>(&Cl[(long)row1 * DHID + col]) = l;
            }
        }
    }
}

__global__ void decoder_kernel(const int* __restrict__ head, const int* __restrict__ tail,
                               const int* __restrict__ rel, const float* __restrict__ h,
                               const float* __restrict__ rel_emb, float* __restrict__ out,
                               int Bn) {
    int warp = (blockIdx.x * blockDim.x + threadIdx.x) >> 5;
    int lane = threadIdx.x & 31;
    if (warp >= Bn) return;
    const float4* hp = reinterpret_cast<const float4*>(h + (long)head[warp] * DHID);
    const float4* tp = reinterpret_cast<const float4*>(h + (long)tail[warp] * DHID);
    const float4* rp = reinterpret_cast<const float4*>(rel_emb + (long)rel[warp] * DHID);
    float4 a = hp[lane], b = tp[lane], c = rp[lane];
    float s = a.x * b.x * c.x + a.y * b.y * c.y + a.z * b.z * c.z + a.w * b.w * c.w;
#pragma unroll
    for (int o = 16; o; o >>= 1) s += __shfl_xor_sync(0xffffffffu, s, o);
    if (lane == 0) out[warp] = s;
}

extern "C" void kernel_launch(void* const* d_in, const int* in_sizes, int n_in,
                              void* d_out, int out_size) {
    const int*   edge_index = (const int*)d_in[0];
    const int*   edge_type  = (const int*)d_in[1];
    const int*   head       = (const int*)d_in[2];
    const int*   tail       = (const int*)d_in[3];
    const int*   rel        = (const int*)d_in[4];
    const float* node_emb   = (const float*)d_in[5];
    const float* W1         = (const float*)d_in[6];
    const float* root1      = (const float*)d_in[7];
    const float* b1         = (const float*)d_in[8];
    const float* W2         = (const float*)d_in[9];
    const float* root2      = (const float*)d_in[10];
    const float* b2         = (const float*)d_in[11];
    const float* rel_emb    = (const float*)d_in[12];

    int E = in_sizes[0] / 2;
    const int* src = edge_index;
    const int* dst = edge_index + E;

    __nv_bfloat16 *xh, *xl, *yh, *yl, *B1h, *B1l, *B2h, *B2l;
    float *h1, *h2;
    int *icnt, *off, *pcur, *bsum, *ebuf;
    cudaGetSymbolAddress((void**)&xh, g_xh);
    cudaGetSymbolAddress((void**)&xl, g_xl);
    cudaGetSymbolAddress((void**)&yh, g_yh);
    cudaGetSymbolAddress((void**)&yl, g_yl);
    cudaGetSymbolAddress((void**)&B1h, g_B1h);
    cudaGetSymbolAddress((void**)&B1l, g_B1l);
    cudaGetSymbolAddress((void**)&B2h, g_B2h);
    cudaGetSymbolAddress((void**)&B2l, g_B2l);
    cudaGetSymbolAddress((void**)&h1, g_h1);
    cudaGetSymbolAddress((void**)&h2, g_h2);
    cudaGetSymbolAddress((void**)&icnt, g_icnt);
    cudaGetSymbolAddress((void**)&off, g_off);
    cudaGetSymbolAddress((void**)&pcur, g_pcur);
    cudaGetSymbolAddress((void**)&bsum, g_bsum);
    cudaGetSymbolAddress((void**)&ebuf, g_ebuf);

    const int T = 256;
    const int KA2 = NRL * DHID;
    const int OFFB = (64 * NRL + 1 + 3) / 4 * 4 * 4;
    const int SM1 = 384 * (DEMB + 8) * 2 + OFFB;   // 60432 B
    const int SM2 = 384 * (DHID + 8) * 2 + OFFB;   // 109584 B -> 2 blocks/SM

    cudaFuncSetAttribute((const void*)fused_gemm_kernel<DEMB, 8, 1>,
                         cudaFuncAttributeMaxDynamicSharedMemorySize, SM1);
    cudaFuncSetAttribute((const void*)fused_gemm_kernel<DHID, 16, 0>,
                         cudaFuncAttributeMaxDynamicSharedMemorySize, SM2);

    // 1) independent prep: X planes + layer-1 B planes
    prep1_kernel<<<592, T>>>(node_emb, xh, xl, W1, root1, B1h, B1l);
    // 2) one-kernel counting sort (grid-resident barrier)
    sort_all_kernel<<<SORT_NB, T>>>(src, dst, edge_type, E, icnt, off, pcur, bsum, ebuf);
    // 3) layer-2 B planes
    prepB_kernel<<<(128 * KT2 / 2 + T - 1) / T, T>>>(W2, root2, KA2, KT2, B2h, B2l);
    // 4) layer 1 fused gather+GEMM (LN=8; epilogue emits h1 planes)
    fused_gemm_kernel<DEMB, 8, 1><<<(NN + 63) / 64, 512, SM1>>>(
        ebuf, off, node_emb, xh, xl, B1h, B1l, b1, h1, yh, yl, 1);
    // 5) layer 2 (LN=16)
    fused_gemm_kernel<DHID, 16, 0><<<(NN + 63) / 64, 512, SM2>>>(
        ebuf, off, h1, yh, yl, B2h, B2l, b2, h2, nullptr, nullptr, 0);
    // 6) DistMult decoder
    int Bn = in_sizes[2];
    decoder_kernel<<<(Bn * 32 + T - 1) / T, T>>>(head, tail, rel, h2, rel_emb,
                                                 (float*)d_out, Bn);
}